// round 2
// baseline (speedup 1.0000x reference)
#include <cuda_runtime.h>

#define Cdim 256
#define Ldim 4096
#define Nb   64
#define MTOT (Nb * Ldim)   // 262144

// ---------------- static device scratch (no runtime allocation) ----------------
__device__ float g_mean[Cdim];
__device__ float g_part[(size_t)Nb * Cdim * Cdim];  // 16 MB: per-n Gram partials
__device__ float g_sigma[Cdim * Cdim];
__device__ float g_scal[4];                          // [0]=C/tr, [1]=rsqrt(tr/C)
__device__ float g_NS[5][Cdim * Cdim];               // 0/1: Y ping-pong, 2/3: Z ping-pong, 4: T

// ---------------- 1) per-channel mean ----------------
__global__ void mean_kernel(const float* __restrict__ X) {
    const int c = blockIdx.x;
    const int t = threadIdx.x;
    float s = 0.0f;
    const float* base = X + (size_t)c * Ldim;
    for (int n = 0; n < Nb; ++n) {
        const float* p = base + (size_t)n * Cdim * Ldim;
        for (int l = t; l < Ldim; l += 256) s += p[l];
    }
    __shared__ float red[256];
    red[t] = s;
    __syncthreads();
    for (int o = 128; o > 0; o >>= 1) {
        if (t < o) red[t] += red[t + o];
        __syncthreads();
    }
    if (t == 0) g_mean[c] = red[0] * (1.0f / (float)MTOT);
}

// ---------------- 2) Gram partials: g_part[n] = X_n @ X_n^T (64x64 tiles) ----------------
__global__ void gram_kernel(const float* __restrict__ X) {
    const int n  = blockIdx.x;       // 0..63 (K-chunk = one batch element)
    const int ti = blockIdx.y >> 2;  // 0..3
    const int tj = blockIdx.y & 3;   // 0..3
    __shared__ float As[64][17];
    __shared__ float Bs[64][17];
    const int t  = threadIdx.x;
    const int tx = t & 15, ty = t >> 4;
    const int lr = t >> 2;           // 0..63
    const int lk = (t & 3) << 2;     // 0,4,8,12
    float acc[4][4] = {};
    const float* Xa = X + (size_t)n * Cdim * Ldim + (size_t)(ti * 64) * Ldim;
    const float* Xb = X + (size_t)n * Cdim * Ldim + (size_t)(tj * 64) * Ldim;

    for (int k0 = 0; k0 < Ldim; k0 += 16) {
        float4 av = *(const float4*)(Xa + (size_t)lr * Ldim + k0 + lk);
        float4 bv = *(const float4*)(Xb + (size_t)lr * Ldim + k0 + lk);
        __syncthreads();
        As[lr][lk + 0] = av.x; As[lr][lk + 1] = av.y; As[lr][lk + 2] = av.z; As[lr][lk + 3] = av.w;
        Bs[lr][lk + 0] = bv.x; Bs[lr][lk + 1] = bv.y; Bs[lr][lk + 2] = bv.z; Bs[lr][lk + 3] = bv.w;
        __syncthreads();
#pragma unroll
        for (int k = 0; k < 16; ++k) {
            float a0 = As[ty * 4 + 0][k];
            float a1 = As[ty * 4 + 1][k];
            float a2 = As[ty * 4 + 2][k];
            float a3 = As[ty * 4 + 3][k];
            float b0 = Bs[tx * 4 + 0][k];
            float b1 = Bs[tx * 4 + 1][k];
            float b2 = Bs[tx * 4 + 2][k];
            float b3 = Bs[tx * 4 + 3][k];
            acc[0][0] += a0 * b0; acc[0][1] += a0 * b1; acc[0][2] += a0 * b2; acc[0][3] += a0 * b3;
            acc[1][0] += a1 * b0; acc[1][1] += a1 * b1; acc[1][2] += a1 * b2; acc[1][3] += a1 * b3;
            acc[2][0] += a2 * b0; acc[2][1] += a2 * b1; acc[2][2] += a2 * b2; acc[2][3] += a2 * b3;
            acc[3][0] += a3 * b0; acc[3][1] += a3 * b1; acc[3][2] += a3 * b2; acc[3][3] += a3 * b3;
        }
    }

    float* outp = g_part + (size_t)n * (Cdim * Cdim);
#pragma unroll
    for (int i = 0; i < 4; ++i)
#pragma unroll
        for (int j = 0; j < 4; ++j)
            outp[(size_t)(ti * 64 + ty * 4 + i) * Cdim + tj * 64 + tx * 4 + j] = acc[i][j];
}

// ---------------- 3) deterministic reduce + sigma = G/m - mu mu^T + eps I ----------------
__global__ void sigma_kernel() {
    const int idx = blockIdx.x * 256 + threadIdx.x;  // 0..65535
    float s = 0.0f;
#pragma unroll 8
    for (int n = 0; n < Nb; ++n) s += g_part[(size_t)n * (Cdim * Cdim) + idx];
    const int i = idx >> 8, j = idx & 255;
    float v = s * (1.0f / (float)MTOT) - g_mean[i] * g_mean[j];
    if (i == j) v += 1e-3f;
    g_sigma[idx] = v;
}

// ---------------- 4) trace -> normalization scalars ----------------
__global__ void trace_kernel() {
    __shared__ float red[256];
    const int t = threadIdx.x;
    red[t] = g_sigma[t * 257];  // diagonal
    __syncthreads();
    for (int o = 128; o > 0; o >>= 1) {
        if (t < o) red[t] += red[t + o];
        __syncthreads();
    }
    if (t == 0) {
        float s = red[0] * (1.0f / 256.0f);  // mean eigenvalue
        g_scal[0] = 1.0f / s;                // A = sigma * g_scal[0]
        g_scal[1] = rsqrtf(s);               // sigma^{-1/2} = Z * g_scal[1]
    }
}

// ---------------- 5) init Y0 = A, Z0 = I ----------------
__global__ void init_kernel() {
    const int idx = blockIdx.x * 256 + threadIdx.x;
    const float inv_s = g_scal[0];
    g_NS[0][idx] = g_sigma[idx] * inv_s;
    g_NS[2][idx] = ((idx >> 8) == (idx & 255)) ? 1.0f : 0.0f;
}

// ---------------- 6) small 256x256x256 GEMM: C = beta*I + alpha*(A@B) ----------------
__global__ void ns_gemm(int ia, int ib, int ic, float alpha, float beta) {
    const float* A = g_NS[ia];
    const float* B = g_NS[ib];
    float* Cm = g_NS[ic];
    const int ti = blockIdx.x >> 2, tj = blockIdx.x & 3;
    __shared__ float As[64][17];
    __shared__ float Bs[16][68];
    const int t  = threadIdx.x;
    const int tx = t & 15, ty = t >> 4;
    float acc[4][4] = {};

    for (int k0 = 0; k0 < 256; k0 += 16) {
        float4 av = *(const float4*)(A + (size_t)(ti * 64 + (t >> 2)) * 256 + k0 + ((t & 3) << 2));
        float4 bv = *(const float4*)(B + (size_t)(k0 + (t >> 4)) * 256 + tj * 64 + ((t & 15) << 2));
        __syncthreads();
        {
            const int ar = t >> 2, ak = (t & 3) << 2;
            As[ar][ak + 0] = av.x; As[ar][ak + 1] = av.y; As[ar][ak + 2] = av.z; As[ar][ak + 3] = av.w;
            *(float4*)&Bs[t >> 4][(t & 15) << 2] = bv;
        }
        __syncthreads();
#pragma unroll
        for (int k = 0; k < 16; ++k) {
            float4 b = *(const float4*)&Bs[k][tx << 2];
            float a0 = As[ty * 4 + 0][k];
            float a1 = As[ty * 4 + 1][k];
            float a2 = As[ty * 4 + 2][k];
            float a3 = As[ty * 4 + 3][k];
            acc[0][0] += a0 * b.x; acc[0][1] += a0 * b.y; acc[0][2] += a0 * b.z; acc[0][3] += a0 * b.w;
            acc[1][0] += a1 * b.x; acc[1][1] += a1 * b.y; acc[1][2] += a1 * b.z; acc[1][3] += a1 * b.w;
            acc[2][0] += a2 * b.x; acc[2][1] += a2 * b.y; acc[2][2] += a2 * b.z; acc[2][3] += a2 * b.w;
            acc[3][0] += a3 * b.x; acc[3][1] += a3 * b.y; acc[3][2] += a3 * b.z; acc[3][3] += a3 * b.w;
        }
    }

#pragma unroll
    for (int i = 0; i < 4; ++i)
#pragma unroll
        for (int j = 0; j < 4; ++j) {
            const int gi = ti * 64 + ty * 4 + i;
            const int gj = tj * 64 + tx * 4 + j;
            Cm[(size_t)gi * 256 + gj] = alpha * acc[i][j] + ((gi == gj) ? beta : 0.0f);
        }
}

// ---------------- 7) whiten: out[n,c,l] = scale * sum_k Z[c,k] * (X[n,k,l] - mu[k]) ----------------
__global__ void whiten_kernel(const float* __restrict__ X, float* __restrict__ out, int iz) {
    const float* W = g_NS[iz];
    const int lt = blockIdx.x;  // 0..31 (128-wide L tile)
    const int ct = blockIdx.y;  // 0..3  (64-row C tile)
    const int n  = blockIdx.z;  // 0..63
    __shared__ float Ws[64][17];
    __shared__ float Xs[16][132];
    const int t  = threadIdx.x;
    const int tx = t & 31, ty = t >> 5;  // tx: 0..31 (4 cols each), ty: 0..7 (8 rows each)
    float acc[8][4] = {};
    const float* Xn = X + (size_t)n * Cdim * Ldim + lt * 128;

    const int kk0 = t >> 5,        j40 = t & 31;        // first 512-float4 half
    const int kk1 = (t >> 5) + 8,  j41 = t & 31;        // second half

    for (int k0 = 0; k0 < 256; k0 += 16) {
        float4 wv  = *(const float4*)(W + (size_t)(ct * 64 + (t >> 2)) * 256 + k0 + ((t & 3) << 2));
        float4 xv0 = *(const float4*)(Xn + (size_t)(k0 + kk0) * Ldim + (j40 << 2));
        float4 xv1 = *(const float4*)(Xn + (size_t)(k0 + kk1) * Ldim + (j41 << 2));
        const float mu0 = g_mean[k0 + kk0];
        const float mu1 = g_mean[k0 + kk1];
        __syncthreads();
        {
            const int wr = t >> 2, wk = (t & 3) << 2;
            Ws[wr][wk + 0] = wv.x; Ws[wr][wk + 1] = wv.y; Ws[wr][wk + 2] = wv.z; Ws[wr][wk + 3] = wv.w;
            xv0.x -= mu0; xv0.y -= mu0; xv0.z -= mu0; xv0.w -= mu0;
            xv1.x -= mu1; xv1.y -= mu1; xv1.z -= mu1; xv1.w -= mu1;
            *(float4*)&Xs[kk0][j40 << 2] = xv0;
            *(float4*)&Xs[kk1][j41 << 2] = xv1;
        }
        __syncthreads();
#pragma unroll
        for (int k = 0; k < 16; ++k) {
            float4 b = *(const float4*)&Xs[k][tx << 2];
#pragma unroll
            for (int i = 0; i < 8; ++i) {
                float a = Ws[ty * 8 + i][k];
                acc[i][0] += a * b.x;
                acc[i][1] += a * b.y;
                acc[i][2] += a * b.z;
                acc[i][3] += a * b.w;
            }
        }
    }

    const float sc = g_scal[1];
    float* ob = out + (size_t)n * Cdim * Ldim + (size_t)(ct * 64) * Ldim + lt * 128;
#pragma unroll
    for (int i = 0; i < 8; ++i) {
        float4 v;
        v.x = acc[i][0] * sc;
        v.y = acc[i][1] * sc;
        v.z = acc[i][2] * sc;
        v.w = acc[i][3] * sc;
        *(float4*)(ob + (size_t)(ty * 8 + i) * Ldim + (tx << 2)) = v;
    }
}

// ---------------- launch ----------------
extern "C" void kernel_launch(void* const* d_in, const int* in_sizes, int n_in,
                              void* d_out, int out_size) {
    const float* X = (const float*)d_in[0];
    float* out = (float*)d_out;

    mean_kernel<<<256, 256>>>(X);
    gram_kernel<<<dim3(64, 16), 256>>>(X);
    sigma_kernel<<<256, 256>>>();
    trace_kernel<<<1, 256>>>();
    init_kernel<<<256, 256>>>();

    // Coupled Newton-Schulz: Y -> A^{1/2}, Z -> A^{-1/2}
    int y = 0, z = 2;
    for (int it = 0; it < 7; ++it) {
        ns_gemm<<<16, 256>>>(z, y, 4, -1.0f, 3.0f);       // T  = 3I - Z@Y
        ns_gemm<<<16, 256>>>(y, 4, y ^ 1, 0.5f, 0.0f);    // Y' = 0.5 * Y@T
        ns_gemm<<<16, 256>>>(4, z, z ^ 1, 0.5f, 0.0f);    // Z' = 0.5 * T@Z
        y ^= 1;
        z ^= 1;
    }

    whiten_kernel<<<dim3(32, 4, 64), 256>>>(X, out, z);
}

// round 3
// speedup vs baseline: 1.0017x; 1.0017x over previous
#include <cuda_runtime.h>

#define Cdim 256
#define Ldim 4096
#define Nb   64
#define MTOT (Nb * Ldim)   // 262144

// ---------------- static device scratch (no runtime allocation) ----------------
__device__ float g_mean[Cdim];
__device__ float g_part[(size_t)Nb * Cdim * Cdim];  // 16 MB: per-n Gram partials
__device__ float g_sigma[Cdim * Cdim];
__device__ float g_scal[4];                          // [0]=C/tr, [1]=rsqrt(tr/C)
__device__ float g_NS[5][Cdim * Cdim];               // 0/1: Y ping-pong, 2/3: Z ping-pong, 4: T

// ---------------- 1) per-channel mean ----------------
__global__ void mean_kernel(const float* __restrict__ X) {
    const int c = blockIdx.x;
    const int t = threadIdx.x;
    float s = 0.0f;
    const float* base = X + (size_t)c * Ldim;
    for (int n = 0; n < Nb; ++n) {
        const float* p = base + (size_t)n * Cdim * Ldim;
        for (int l = t; l < Ldim; l += 256) s += p[l];
    }
    __shared__ float red[256];
    red[t] = s;
    __syncthreads();
    for (int o = 128; o > 0; o >>= 1) {
        if (t < o) red[t] += red[t + o];
        __syncthreads();
    }
    if (t == 0) g_mean[c] = red[0] * (1.0f / (float)MTOT);
}

// ---------------- 2) Gram partials: g_part[n] = X_n @ X_n^T (64x64 tiles) ----------------
__global__ void gram_kernel(const float* __restrict__ X) {
    const int n  = blockIdx.x;       // 0..63 (K-chunk = one batch element)
    const int ti = blockIdx.y >> 2;  // 0..3
    const int tj = blockIdx.y & 3;   // 0..3
    __shared__ float As[64][17];
    __shared__ float Bs[64][17];
    const int t  = threadIdx.x;
    const int tx = t & 15, ty = t >> 4;
    const int lr = t >> 2;           // 0..63
    const int lk = (t & 3) << 2;     // 0,4,8,12
    float acc[4][4] = {};
    const float* Xa = X + (size_t)n * Cdim * Ldim + (size_t)(ti * 64) * Ldim;
    const float* Xb = X + (size_t)n * Cdim * Ldim + (size_t)(tj * 64) * Ldim;

    for (int k0 = 0; k0 < Ldim; k0 += 16) {
        float4 av = *(const float4*)(Xa + (size_t)lr * Ldim + k0 + lk);
        float4 bv = *(const float4*)(Xb + (size_t)lr * Ldim + k0 + lk);
        __syncthreads();
        As[lr][lk + 0] = av.x; As[lr][lk + 1] = av.y; As[lr][lk + 2] = av.z; As[lr][lk + 3] = av.w;
        Bs[lr][lk + 0] = bv.x; Bs[lr][lk + 1] = bv.y; Bs[lr][lk + 2] = bv.z; Bs[lr][lk + 3] = bv.w;
        __syncthreads();
#pragma unroll
        for (int k = 0; k < 16; ++k) {
            float a0 = As[ty * 4 + 0][k];
            float a1 = As[ty * 4 + 1][k];
            float a2 = As[ty * 4 + 2][k];
            float a3 = As[ty * 4 + 3][k];
            float b0 = Bs[tx * 4 + 0][k];
            float b1 = Bs[tx * 4 + 1][k];
            float b2 = Bs[tx * 4 + 2][k];
            float b3 = Bs[tx * 4 + 3][k];
            acc[0][0] += a0 * b0; acc[0][1] += a0 * b1; acc[0][2] += a0 * b2; acc[0][3] += a0 * b3;
            acc[1][0] += a1 * b0; acc[1][1] += a1 * b1; acc[1][2] += a1 * b2; acc[1][3] += a1 * b3;
            acc[2][0] += a2 * b0; acc[2][1] += a2 * b1; acc[2][2] += a2 * b2; acc[2][3] += a2 * b3;
            acc[3][0] += a3 * b0; acc[3][1] += a3 * b1; acc[3][2] += a3 * b2; acc[3][3] += a3 * b3;
        }
    }

    float* outp = g_part + (size_t)n * (Cdim * Cdim);
#pragma unroll
    for (int i = 0; i < 4; ++i)
#pragma unroll
        for (int j = 0; j < 4; ++j)
            outp[(size_t)(ti * 64 + ty * 4 + i) * Cdim + tj * 64 + tx * 4 + j] = acc[i][j];
}

// ---------------- 3) deterministic reduce + sigma = G/m - mu mu^T + eps I ----------------
__global__ void sigma_kernel() {
    const int idx = blockIdx.x * 256 + threadIdx.x;  // 0..65535
    float s = 0.0f;
#pragma unroll 8
    for (int n = 0; n < Nb; ++n) s += g_part[(size_t)n * (Cdim * Cdim) + idx];
    const int i = idx >> 8, j = idx & 255;
    float v = s * (1.0f / (float)MTOT) - g_mean[i] * g_mean[j];
    if (i == j) v += 1e-3f;
    g_sigma[idx] = v;
}

// ---------------- 4) trace -> normalization scalars ----------------
__global__ void trace_kernel() {
    __shared__ float red[256];
    const int t = threadIdx.x;
    red[t] = g_sigma[t * 257];  // diagonal
    __syncthreads();
    for (int o = 128; o > 0; o >>= 1) {
        if (t < o) red[t] += red[t + o];
        __syncthreads();
    }
    if (t == 0) {
        float s = red[0] * (1.0f / 256.0f);  // mean eigenvalue
        g_scal[0] = 1.0f / s;                // A = sigma * g_scal[0]
        g_scal[1] = rsqrtf(s);               // sigma^{-1/2} = Z * g_scal[1]
    }
}

// ---------------- 5) init Y0 = A, Z0 = I ----------------
__global__ void init_kernel() {
    const int idx = blockIdx.x * 256 + threadIdx.x;
    const float inv_s = g_scal[0];
    g_NS[0][idx] = g_sigma[idx] * inv_s;
    g_NS[2][idx] = ((idx >> 8) == (idx & 255)) ? 1.0f : 0.0f;
}

// ---------------- 6) small 256x256x256 GEMM: C = beta*I + alpha*(A@B) ----------------
__global__ void ns_gemm(int ia, int ib, int ic, float alpha, float beta) {
    const float* A = g_NS[ia];
    const float* B = g_NS[ib];
    float* Cm = g_NS[ic];
    const int ti = blockIdx.x >> 2, tj = blockIdx.x & 3;
    __shared__ float As[64][17];
    __shared__ float Bs[16][68];
    const int t  = threadIdx.x;
    const int tx = t & 15, ty = t >> 4;
    float acc[4][4] = {};

    for (int k0 = 0; k0 < 256; k0 += 16) {
        float4 av = *(const float4*)(A + (size_t)(ti * 64 + (t >> 2)) * 256 + k0 + ((t & 3) << 2));
        float4 bv = *(const float4*)(B + (size_t)(k0 + (t >> 4)) * 256 + tj * 64 + ((t & 15) << 2));
        __syncthreads();
        {
            const int ar = t >> 2, ak = (t & 3) << 2;
            As[ar][ak + 0] = av.x; As[ar][ak + 1] = av.y; As[ar][ak + 2] = av.z; As[ar][ak + 3] = av.w;
            *(float4*)&Bs[t >> 4][(t & 15) << 2] = bv;
        }
        __syncthreads();
#pragma unroll
        for (int k = 0; k < 16; ++k) {
            float4 b = *(const float4*)&Bs[k][tx << 2];
            float a0 = As[ty * 4 + 0][k];
            float a1 = As[ty * 4 + 1][k];
            float a2 = As[ty * 4 + 2][k];
            float a3 = As[ty * 4 + 3][k];
            acc[0][0] += a0 * b.x; acc[0][1] += a0 * b.y; acc[0][2] += a0 * b.z; acc[0][3] += a0 * b.w;
            acc[1][0] += a1 * b.x; acc[1][1] += a1 * b.y; acc[1][2] += a1 * b.z; acc[1][3] += a1 * b.w;
            acc[2][0] += a2 * b.x; acc[2][1] += a2 * b.y; acc[2][2] += a2 * b.z; acc[2][3] += a2 * b.w;
            acc[3][0] += a3 * b.x; acc[3][1] += a3 * b.y; acc[3][2] += a3 * b.z; acc[3][3] += a3 * b.w;
        }
    }

#pragma unroll
    for (int i = 0; i < 4; ++i)
#pragma unroll
        for (int j = 0; j < 4; ++j) {
            const int gi = ti * 64 + ty * 4 + i;
            const int gj = tj * 64 + tx * 4 + j;
            Cm[(size_t)gi * 256 + gj] = alpha * acc[i][j] + ((gi == gj) ? beta : 0.0f);
        }
}

// ---------------- 7) whiten: out[n,c,l] = scale * sum_k Z[c,k] * (X[n,k,l] - mu[k]) ----------------
__global__ void whiten_kernel(const float* __restrict__ X, float* __restrict__ out, int iz) {
    const float* W = g_NS[iz];
    const int lt = blockIdx.x;  // 0..31 (128-wide L tile)
    const int ct = blockIdx.y;  // 0..3  (64-row C tile)
    const int n  = blockIdx.z;  // 0..63
    __shared__ float Ws[64][17];
    __shared__ float Xs[16][132];
    const int t  = threadIdx.x;
    const int tx = t & 31, ty = t >> 5;  // tx: 0..31 (4 cols each), ty: 0..7 (8 rows each)
    float acc[8][4] = {};
    const float* Xn = X + (size_t)n * Cdim * Ldim + lt * 128;

    const int kk0 = t >> 5,        j40 = t & 31;        // first 512-float4 half
    const int kk1 = (t >> 5) + 8,  j41 = t & 31;        // second half

    for (int k0 = 0; k0 < 256; k0 += 16) {
        float4 wv  = *(const float4*)(W + (size_t)(ct * 64 + (t >> 2)) * 256 + k0 + ((t & 3) << 2));
        float4 xv0 = *(const float4*)(Xn + (size_t)(k0 + kk0) * Ldim + (j40 << 2));
        float4 xv1 = *(const float4*)(Xn + (size_t)(k0 + kk1) * Ldim + (j41 << 2));
        const float mu0 = g_mean[k0 + kk0];
        const float mu1 = g_mean[k0 + kk1];
        __syncthreads();
        {
            const int wr = t >> 2, wk = (t & 3) << 2;
            Ws[wr][wk + 0] = wv.x; Ws[wr][wk + 1] = wv.y; Ws[wr][wk + 2] = wv.z; Ws[wr][wk + 3] = wv.w;
            xv0.x -= mu0; xv0.y -= mu0; xv0.z -= mu0; xv0.w -= mu0;
            xv1.x -= mu1; xv1.y -= mu1; xv1.z -= mu1; xv1.w -= mu1;
            *(float4*)&Xs[kk0][j40 << 2] = xv0;
            *(float4*)&Xs[kk1][j41 << 2] = xv1;
        }
        __syncthreads();
#pragma unroll
        for (int k = 0; k < 16; ++k) {
            float4 b = *(const float4*)&Xs[k][tx << 2];
#pragma unroll
            for (int i = 0; i < 8; ++i) {
                float a = Ws[ty * 8 + i][k];
                acc[i][0] += a * b.x;
                acc[i][1] += a * b.y;
                acc[i][2] += a * b.z;
                acc[i][3] += a * b.w;
            }
        }
    }

    const float sc = g_scal[1];
    float* ob = out + (size_t)n * Cdim * Ldim + (size_t)(ct * 64) * Ldim + lt * 128;
#pragma unroll
    for (int i = 0; i < 8; ++i) {
        float4 v;
        v.x = acc[i][0] * sc;
        v.y = acc[i][1] * sc;
        v.z = acc[i][2] * sc;
        v.w = acc[i][3] * sc;
        *(float4*)(ob + (size_t)(ty * 8 + i) * Ldim + (tx << 2)) = v;
    }
}

// ---------------- launch ----------------
extern "C" void kernel_launch(void* const* d_in, const int* in_sizes, int n_in,
                              void* d_out, int out_size) {
    const float* X = (const float*)d_in[0];
    float* out = (float*)d_out;

    mean_kernel<<<256, 256>>>(X);
    gram_kernel<<<dim3(64, 16), 256>>>(X);
    sigma_kernel<<<256, 256>>>();
    trace_kernel<<<1, 256>>>();
    init_kernel<<<256, 256>>>();

    // Coupled Newton-Schulz: Y -> A^{1/2}, Z -> A^{-1/2}
    int y = 0, z = 2;
    for (int it = 0; it < 7; ++it) {
        ns_gemm<<<16, 256>>>(z, y, 4, -1.0f, 3.0f);       // T  = 3I - Z@Y
        ns_gemm<<<16, 256>>>(y, 4, y ^ 1, 0.5f, 0.0f);    // Y' = 0.5 * Y@T
        ns_gemm<<<16, 256>>>(4, z, z ^ 1, 0.5f, 0.0f);    // Z' = 0.5 * T@Z
        y ^= 1;
        z ^= 1;
    }

    whiten_kernel<<<dim3(32, 4, 64), 256>>>(X, out, z);
}

// round 5
// speedup vs baseline: 4.5171x; 4.5097x over previous
#include <cuda_runtime.h>
#include <cuda_bf16.h>
#include <cstdint>

#define Cdim 256
#define Ldim 4096
#define Nb   64
#define MTOT (Nb * Ldim)

// ---------------- static device scratch ----------------
__device__ __nv_bfloat16 g_Xh[(size_t)Nb * Cdim * Ldim];  // 128 MB bf16 copy of X
__device__ float g_part[3][Nb][128 * 128];                // gram partials
__device__ float g_msum[Cdim * Nb];
__device__ float g_mean[Cdim];
__device__ float g_sigma[Cdim * Cdim];
__device__ float g_scal[4];
__device__ float g_NS[5][Cdim * Cdim];
__device__ __nv_bfloat16 g_Ebf[Cdim * Cdim];              // E = sc*Z - I in bf16
__device__ float g_b[Cdim];

// ---------------- PTX helpers (all plain sm_80+ features) ----------------
__device__ __forceinline__ uint32_t smem_u32(const void* p) {
    uint32_t a;
    asm("{ .reg .u64 t; cvta.to.shared.u64 t, %1; cvt.u32.u64 %0, t; }" : "=r"(a) : "l"(p));
    return a;
}
__device__ __forceinline__ void mma16816(float* d, const uint32_t* a, const uint32_t* b) {
    asm volatile(
        "mma.sync.aligned.m16n8k16.row.col.f32.bf16.bf16.f32 "
        "{%0,%1,%2,%3}, {%4,%5,%6,%7}, {%8,%9}, {%0,%1,%2,%3};"
        : "+f"(d[0]), "+f"(d[1]), "+f"(d[2]), "+f"(d[3])
        : "r"(a[0]), "r"(a[1]), "r"(a[2]), "r"(a[3]), "r"(b[0]), "r"(b[1]));
}
__device__ __forceinline__ void ldsm4(uint32_t* r, uint32_t addr) {
    asm volatile("ldmatrix.sync.aligned.m8n8.x4.shared.b16 {%0,%1,%2,%3}, [%4];"
                 : "=r"(r[0]), "=r"(r[1]), "=r"(r[2]), "=r"(r[3]) : "r"(addr));
}
__device__ __forceinline__ void ldsm2(uint32_t* r, uint32_t addr) {
    asm volatile("ldmatrix.sync.aligned.m8n8.x2.shared.b16 {%0,%1}, [%2];"
                 : "=r"(r[0]), "=r"(r[1]) : "r"(addr));
}
__device__ __forceinline__ void ldsm2t(uint32_t* r, uint32_t addr) {
    asm volatile("ldmatrix.sync.aligned.m8n8.x2.trans.shared.b16 {%0,%1}, [%2];"
                 : "=r"(r[0]), "=r"(r[1]) : "r"(addr));
}
__device__ __forceinline__ void cpasync16(uint32_t smem, const void* g) {
    asm volatile("cp.async.cg.shared.global [%0], [%1], 16;" :: "r"(smem), "l"(g));
}
__device__ __forceinline__ void cpcommit() { asm volatile("cp.async.commit_group;" ::: "memory"); }
template <int N>
__device__ __forceinline__ void cpwait() {
    asm volatile("cp.async.wait_group %0;" :: "n"(N) : "memory");
}

// ---------------- 1) convert X -> bf16, per-row partial sums ----------------
__global__ void conv_kernel(const float* __restrict__ X) {
    const size_t row = blockIdx.x;  // n*Cdim + c
    const int t = threadIdx.x;
    const float4* src = (const float4*)(X + row * (size_t)Ldim);
    uint4* dst = (uint4*)(g_Xh + row * (size_t)Ldim);
    float s = 0.0f;
#pragma unroll
    for (int i = 0; i < 2; ++i) {
        float4 a = src[4 * t + 2 * i];
        float4 b = src[4 * t + 2 * i + 1];
        s += a.x + a.y + a.z + a.w + b.x + b.y + b.z + b.w;
        uint4 o;
        __nv_bfloat162 h;
        h = __floats2bfloat162_rn(a.x, a.y); o.x = *(uint32_t*)&h;
        h = __floats2bfloat162_rn(a.z, a.w); o.y = *(uint32_t*)&h;
        h = __floats2bfloat162_rn(b.x, b.y); o.z = *(uint32_t*)&h;
        h = __floats2bfloat162_rn(b.z, b.w); o.w = *(uint32_t*)&h;
        dst[2 * t + i] = o;
    }
    __shared__ float red[256];
    red[t] = s;
    __syncthreads();
    for (int o = 128; o > 0; o >>= 1) {
        if (t < o) red[t] += red[t + o];
        __syncthreads();
    }
    if (t == 0) g_msum[row] = red[0];
}

__global__ void mean_reduce() {
    const int c = threadIdx.x;
    float s = 0.0f;
    for (int n = 0; n < Nb; ++n) s += g_msum[(size_t)n * Cdim + c];
    g_mean[c] = s * (1.0f / (float)MTOT);
}

// ---------------- 2) Gram via mma.sync: 3 tiles x 64 K-splits ----------------
#define GP 144  // gram smem row pitch (64 bf16 = 128B + 16B pad)
__device__ __forceinline__ void gram_prefetch(uint32_t offA, uint32_t offB,
                                              const char* Ag, const char* Bg,
                                              int t, int kb) {
#pragma unroll
    for (int i = 0; i < 4; ++i) {
        int slot = t + 256 * i;
        int row = slot >> 3, c16 = (slot & 7) * 16;
        cpasync16(offA + row * GP + c16, Ag + (size_t)row * 8192 + kb + c16);
        cpasync16(offB + row * GP + c16, Bg + (size_t)row * 8192 + kb + c16);
    }
}

__global__ __launch_bounds__(256) void gram_kernel() {
    extern __shared__ __align__(128) char sm[];
    const uint32_t sb = smem_u32(sm);
    const int t = threadIdx.x;
    const int warp = t >> 5, lane = t & 31;
    const int wm = warp >> 2, wn = warp & 3;  // 2 x 4 warp grid, warp tile 64x32
    const int tile = blockIdx.x, n = blockIdx.y;
    const int ti = (tile == 0) ? 0 : 1;
    const int tj = (tile == 2) ? 1 : 0;
    const uint32_t offA[2] = {sb, sb + 36864};
    const uint32_t offB[2] = {sb + 18432, sb + 55296};

    const char* Ag = (const char*)(g_Xh + ((size_t)n * Cdim + ti * 128) * Ldim);
    const char* Bg = (const char*)(g_Xh + ((size_t)n * Cdim + tj * 128) * Ldim);

    float acc[4][4][4];
#pragma unroll
    for (int i = 0; i < 4; ++i)
#pragma unroll
        for (int j = 0; j < 4; ++j)
#pragma unroll
            for (int r = 0; r < 4; ++r) acc[i][j][r] = 0.0f;

    gram_prefetch(offA[0], offB[0], Ag, Bg, t, 0);
    cpcommit();
    gram_prefetch(offA[1], offB[1], Ag, Bg, t, 128);
    cpcommit();

    for (int s = 0; s < 64; ++s) {
        if (s == 63) cpwait<0>(); else cpwait<1>();
        __syncthreads();
        const uint32_t sa = offA[s & 1], sbuf = offB[s & 1];
#pragma unroll
        for (int ks = 0; ks < 4; ++ks) {
            uint32_t afrag[4][4], bfrag[4][2];
#pragma unroll
            for (int mi = 0; mi < 4; ++mi)
                ldsm4(afrag[mi], sa + (wm * 64 + mi * 16 + (lane & 15)) * GP +
                                     ks * 32 + ((lane >> 4) * 16));
#pragma unroll
            for (int ni = 0; ni < 4; ++ni)
                ldsm2(bfrag[ni], sbuf + (wn * 32 + ni * 8 + (lane & 7)) * GP +
                                     ks * 32 + (((lane >> 3) & 1) * 16));
#pragma unroll
            for (int mi = 0; mi < 4; ++mi)
#pragma unroll
                for (int ni = 0; ni < 4; ++ni)
                    mma16816(acc[mi][ni], afrag[mi], bfrag[ni]);
        }
        __syncthreads();
        if (s + 2 < 64) {
            gram_prefetch(offA[s & 1], offB[s & 1], Ag, Bg, t, (s + 2) * 128);
            cpcommit();
        }
    }

    float* outp = g_part[tile][n];
#pragma unroll
    for (int mi = 0; mi < 4; ++mi)
#pragma unroll
        for (int ni = 0; ni < 4; ++ni) {
            int r0 = wm * 64 + mi * 16 + (lane >> 2);
            int c0 = wn * 32 + ni * 8 + (lane & 3) * 2;
            *(float2*)(outp + r0 * 128 + c0)       = make_float2(acc[mi][ni][0], acc[mi][ni][1]);
            *(float2*)(outp + (r0 + 8) * 128 + c0) = make_float2(acc[mi][ni][2], acc[mi][ni][3]);
        }
}

// ---------------- 3) sigma assembly ----------------
__global__ void sigma_kernel() {
    const int idx = blockIdx.x * 256 + threadIdx.x;
    const int i = idx >> 8, j = idx & 255;
    int tile, ii, jj;
    if (i < 128 && j < 128)        { tile = 0; ii = i;       jj = j; }
    else if (i >= 128 && j < 128)  { tile = 1; ii = i - 128; jj = j; }
    else if (i >= 128 && j >= 128) { tile = 2; ii = i - 128; jj = j - 128; }
    else                           { tile = 1; ii = j - 128; jj = i; }  // symmetry
    float s = 0.0f;
#pragma unroll 4
    for (int n = 0; n < Nb; ++n) s += g_part[tile][n][ii * 128 + jj];
    float v = s * (1.0f / (float)MTOT) - g_mean[i] * g_mean[j];
    if (i == j) v += 1e-3f;
    g_sigma[idx] = v;
}

__global__ void trace_kernel() {
    __shared__ float red[256];
    const int t = threadIdx.x;
    red[t] = g_sigma[t * 257];
    __syncthreads();
    for (int o = 128; o > 0; o >>= 1) {
        if (t < o) red[t] += red[t + o];
        __syncthreads();
    }
    if (t == 0) {
        float s = red[0] * (1.0f / 256.0f);
        g_scal[0] = 1.0f / s;
        g_scal[1] = rsqrtf(s);
    }
}

__global__ void init_kernel() {
    const int idx = blockIdx.x * 256 + threadIdx.x;
    g_NS[0][idx] = g_sigma[idx] * g_scal[0];
    g_NS[2][idx] = ((idx >> 8) == (idx & 255)) ? 1.0f : 0.0f;
}

// ---------------- 4) fp32 256^3 GEMM body for Newton-Schulz ----------------
__device__ __forceinline__ void ns_body(int tileIdx, const float* A, const float* B,
                                        float* Cm, float alpha, float beta) {
    const int ti = tileIdx >> 2, tj = tileIdx & 3;
    __shared__ float As[64][17];
    __shared__ float Bs[16][68];
    const int t = threadIdx.x;
    const int tx = t & 15, ty = t >> 4;
    float acc[4][4] = {};
    for (int k0 = 0; k0 < 256; k0 += 16) {
        float4 av = *(const float4*)(A + (size_t)(ti * 64 + (t >> 2)) * 256 + k0 + ((t & 3) << 2));
        float4 bv = *(const float4*)(B + (size_t)(k0 + (t >> 4)) * 256 + tj * 64 + ((t & 15) << 2));
        __syncthreads();
        {
            const int ar = t >> 2, ak = (t & 3) << 2;
            As[ar][ak + 0] = av.x; As[ar][ak + 1] = av.y; As[ar][ak + 2] = av.z; As[ar][ak + 3] = av.w;
            *(float4*)&Bs[t >> 4][(t & 15) << 2] = bv;
        }
        __syncthreads();
#pragma unroll
        for (int k = 0; k < 16; ++k) {
            float4 b = *(const float4*)&Bs[k][tx << 2];
            float a0 = As[ty * 4 + 0][k], a1 = As[ty * 4 + 1][k];
            float a2 = As[ty * 4 + 2][k], a3 = As[ty * 4 + 3][k];
            acc[0][0] += a0 * b.x; acc[0][1] += a0 * b.y; acc[0][2] += a0 * b.z; acc[0][3] += a0 * b.w;
            acc[1][0] += a1 * b.x; acc[1][1] += a1 * b.y; acc[1][2] += a1 * b.z; acc[1][3] += a1 * b.w;
            acc[2][0] += a2 * b.x; acc[2][1] += a2 * b.y; acc[2][2] += a2 * b.z; acc[2][3] += a2 * b.w;
            acc[3][0] += a3 * b.x; acc[3][1] += a3 * b.y; acc[3][2] += a3 * b.z; acc[3][3] += a3 * b.w;
        }
    }
#pragma unroll
    for (int i = 0; i < 4; ++i)
#pragma unroll
        for (int j = 0; j < 4; ++j) {
            const int gi = ti * 64 + ty * 4 + i;
            const int gj = tj * 64 + tx * 4 + j;
            Cm[(size_t)gi * 256 + gj] = alpha * acc[i][j] + ((gi == gj) ? beta : 0.0f);
        }
}

__global__ void ns_T(int iz, int iy) {  // T = 3I - Z@Y
    ns_body(blockIdx.x, g_NS[iz], g_NS[iy], g_NS[4], -1.0f, 3.0f);
}
__global__ void ns_YZ(int iy, int iz) {  // Y' = 0.5 Y@T ; Z' = 0.5 T@Z
    if (blockIdx.x < 16)
        ns_body(blockIdx.x, g_NS[iy], g_NS[4], g_NS[iy ^ 1], 0.5f, 0.0f);
    else
        ns_body(blockIdx.x - 16, g_NS[4], g_NS[iz], g_NS[iz ^ 1], 0.5f, 0.0f);
}

// ---------------- 5) E = sc*Z - I (bf16) and b = mu + E mu ----------------
__global__ void bE_kernel(int iz) {
    const int c = blockIdx.x, t = threadIdx.x;
    const float sc = g_scal[1];
    float e = sc * g_NS[iz][c * 256 + t] - ((c == t) ? 1.0f : 0.0f);
    g_Ebf[c * 256 + t] = __float2bfloat16(e);
    __shared__ float red[256];
    red[t] = e * g_mean[t];
    __syncthreads();
    for (int o = 128; o > 0; o >>= 1) {
        if (t < o) red[t] += red[t + o];
        __syncthreads();
    }
    if (t == 0) g_b[c] = g_mean[c] + red[0];
}

// ---------------- 6) whiten: out = x - b + E @ x_bf16 (mma.sync, trans B) ----------------
#define WPA 528  // E tile pitch: 256 bf16 = 512B + 16
#define WPB 272  // x tile pitch: 128 bf16 = 256B + 16
__global__ __launch_bounds__(512) void whiten_kernel(const float* __restrict__ X,
                                                     float* __restrict__ out) {
    extern __shared__ __align__(128) char sm[];
    const uint32_t sb = smem_u32(sm);
    const int t = threadIdx.x;
    const int warp = t >> 5, lane = t & 31;
    const int wm = warp >> 2, wn = warp & 3;  // 4 x 4 warp grid, warp tile 64x32
    const int n = blockIdx.x >> 5, l0 = (blockIdx.x & 31) * 128;
    const uint32_t sA = sb, sB = sb + 256 * WPA;

    // load full E (256x256 bf16) and x tile (256 k-rows x 128 l-cols bf16)
    const char* Eg = (const char*)g_Ebf;
#pragma unroll
    for (int i = 0; i < 16; ++i) {
        int slot = t + 512 * i;
        int row = slot >> 5, c16 = (slot & 31) * 16;
        cpasync16(sA + row * WPA + c16, Eg + (size_t)row * 512 + c16);
    }
    const char* Bg = (const char*)(g_Xh + (size_t)n * Cdim * Ldim + l0);
#pragma unroll
    for (int i = 0; i < 8; ++i) {
        int slot = t + 512 * i;
        int row = slot >> 4, c16 = (slot & 15) * 16;
        cpasync16(sB + row * WPB + c16, Bg + (size_t)row * 8192 + c16);
    }
    cpcommit();
    cpwait<0>();
    __syncthreads();

    float acc[4][4][4];
#pragma unroll
    for (int i = 0; i < 4; ++i)
#pragma unroll
        for (int j = 0; j < 4; ++j)
#pragma unroll
            for (int r = 0; r < 4; ++r) acc[i][j][r] = 0.0f;

#pragma unroll 4
    for (int ks = 0; ks < 16; ++ks) {
        uint32_t afrag[4][4], bfrag[4][2];
#pragma unroll
        for (int mi = 0; mi < 4; ++mi)
            ldsm4(afrag[mi], sA + (wm * 64 + mi * 16 + (lane & 15)) * WPA +
                                 ks * 32 + ((lane >> 4) * 16));
#pragma unroll
        for (int ni = 0; ni < 4; ++ni)
            ldsm2t(bfrag[ni], sB + (ks * 16 + (lane & 15)) * WPB +
                                  (wn * 32 + ni * 8) * 2);
#pragma unroll
        for (int mi = 0; mi < 4; ++mi)
#pragma unroll
            for (int ni = 0; ni < 4; ++ni)
                mma16816(acc[mi][ni], afrag[mi], bfrag[ni]);
    }

    // epilogue: out[c][l] = acc + x - b
#pragma unroll
    for (int mi = 0; mi < 4; ++mi) {
        const int r0 = wm * 64 + mi * 16 + (lane >> 2);
        const float b0 = g_b[r0], b1 = g_b[r0 + 8];
        const float* x0 = X + ((size_t)n * Cdim + r0) * Ldim + l0;
        float* o0 = out + ((size_t)n * Cdim + r0) * Ldim + l0;
#pragma unroll
        for (int ni = 0; ni < 4; ++ni) {
            const int c = wn * 32 + ni * 8 + (lane & 3) * 2;
            float2 xv0 = *(const float2*)(x0 + c);
            float2 xv1 = *(const float2*)(x0 + 8 * Ldim + c);
            float2 ov0, ov1;
            ov0.x = acc[mi][ni][0] + xv0.x - b0;
            ov0.y = acc[mi][ni][1] + xv0.y - b0;
            ov1.x = acc[mi][ni][2] + xv1.x - b1;
            ov1.y = acc[mi][ni][3] + xv1.y - b1;
            *(float2*)(o0 + c) = ov0;
            *(float2*)(o0 + 8 * Ldim + c) = ov1;
        }
    }
}

// ---------------- launch ----------------
extern "C" void kernel_launch(void* const* d_in, const int* in_sizes, int n_in,
                              void* d_out, int out_size) {
    const float* X = (const float*)d_in[0];
    float* out = (float*)d_out;

    cudaFuncSetAttribute(gram_kernel, cudaFuncAttributeMaxDynamicSharedMemorySize, 73728);
    cudaFuncSetAttribute(whiten_kernel, cudaFuncAttributeMaxDynamicSharedMemorySize, 204800);

    conv_kernel<<<Nb * Cdim, 256>>>(X);
    mean_reduce<<<1, 256>>>();
    gram_kernel<<<dim3(3, Nb), 256, 73728>>>();
    sigma_kernel<<<256, 256>>>();
    trace_kernel<<<1, 256>>>();
    init_kernel<<<256, 256>>>();

    int y = 0, z = 2;
    for (int it = 0; it < 4; ++it) {
        ns_T<<<16, 256>>>(z, y);
        ns_YZ<<<32, 256>>>(y, z);
        y ^= 1;
        z ^= 1;
    }

    bE_kernel<<<256, 256>>>(z);
    whiten_kernel<<<2048, 512, 204800>>>(X, out);
}

// round 6
// speedup vs baseline: 4.8937x; 1.0834x over previous
#include <cuda_runtime.h>
#include <cuda_bf16.h>
#include <cstdint>

#define Cdim 256
#define Ldim 4096
#define Nb   64
#define MTOT (Nb * Ldim)

// ---------------- static device scratch ----------------
__device__ __nv_bfloat16 g_Xh[(size_t)Nb * Cdim * Ldim];  // 128 MB bf16 copy of X
__device__ float g_part[3][Nb][128 * 128];                // gram partials
__device__ float g_msum[Cdim * Nb];
__device__ float g_mean[Cdim];
__device__ float g_sigma[Cdim * Cdim];
__device__ float g_scal[4];
__device__ float g_NS[5][Cdim * Cdim];
__device__ __nv_bfloat16 g_Ebf[Cdim * Cdim];              // E = sc*Z - I in bf16
__device__ float g_b[Cdim];

// ---------------- PTX helpers (all plain sm_80+ features) ----------------
__device__ __forceinline__ uint32_t smem_u32(const void* p) {
    uint32_t a;
    asm("{ .reg .u64 t; cvta.to.shared.u64 t, %1; cvt.u32.u64 %0, t; }" : "=r"(a) : "l"(p));
    return a;
}
__device__ __forceinline__ void mma16816(float* d, const uint32_t* a, const uint32_t* b) {
    asm volatile(
        "mma.sync.aligned.m16n8k16.row.col.f32.bf16.bf16.f32 "
        "{%0,%1,%2,%3}, {%4,%5,%6,%7}, {%8,%9}, {%0,%1,%2,%3};"
        : "+f"(d[0]), "+f"(d[1]), "+f"(d[2]), "+f"(d[3])
        : "r"(a[0]), "r"(a[1]), "r"(a[2]), "r"(a[3]), "r"(b[0]), "r"(b[1]));
}
__device__ __forceinline__ void ldsm4(uint32_t* r, uint32_t addr) {
    asm volatile("ldmatrix.sync.aligned.m8n8.x4.shared.b16 {%0,%1,%2,%3}, [%4];"
                 : "=r"(r[0]), "=r"(r[1]), "=r"(r[2]), "=r"(r[3]) : "r"(addr));
}
__device__ __forceinline__ void ldsm2(uint32_t* r, uint32_t addr) {
    asm volatile("ldmatrix.sync.aligned.m8n8.x2.shared.b16 {%0,%1}, [%2];"
                 : "=r"(r[0]), "=r"(r[1]) : "r"(addr));
}
__device__ __forceinline__ void ldsm2t(uint32_t* r, uint32_t addr) {
    asm volatile("ldmatrix.sync.aligned.m8n8.x2.trans.shared.b16 {%0,%1}, [%2];"
                 : "=r"(r[0]), "=r"(r[1]) : "r"(addr));
}
__device__ __forceinline__ void cpasync16(uint32_t smem, const void* g) {
    asm volatile("cp.async.cg.shared.global [%0], [%1], 16;" :: "r"(smem), "l"(g));
}
__device__ __forceinline__ void cpcommit() { asm volatile("cp.async.commit_group;" ::: "memory"); }
template <int N>
__device__ __forceinline__ void cpwait() {
    asm volatile("cp.async.wait_group %0;" :: "n"(N) : "memory");
}

// ---------------- 1) convert X -> bf16, per-row partial sums ----------------
__global__ void conv_kernel(const float* __restrict__ X) {
    const size_t row = blockIdx.x;  // n*Cdim + c
    const int t = threadIdx.x;
    const float4* src = (const float4*)(X + row * (size_t)Ldim);
    uint4* dst = (uint4*)(g_Xh + row * (size_t)Ldim);
    float s = 0.0f;
#pragma unroll
    for (int i = 0; i < 2; ++i) {
        float4 a = src[4 * t + 2 * i];
        float4 b = src[4 * t + 2 * i + 1];
        s += a.x + a.y + a.z + a.w + b.x + b.y + b.z + b.w;
        uint4 o;
        __nv_bfloat162 h;
        h = __floats2bfloat162_rn(a.x, a.y); o.x = *(uint32_t*)&h;
        h = __floats2bfloat162_rn(a.z, a.w); o.y = *(uint32_t*)&h;
        h = __floats2bfloat162_rn(b.x, b.y); o.z = *(uint32_t*)&h;
        h = __floats2bfloat162_rn(b.z, b.w); o.w = *(uint32_t*)&h;
        dst[2 * t + i] = o;
    }
    __shared__ float red[256];
    red[t] = s;
    __syncthreads();
    for (int o = 128; o > 0; o >>= 1) {
        if (t < o) red[t] += red[t + o];
        __syncthreads();
    }
    if (t == 0) g_msum[row] = red[0];
}

__global__ void mean_reduce() {
    const int c = threadIdx.x;
    float s = 0.0f;
    for (int n = 0; n < Nb; ++n) s += g_msum[(size_t)n * Cdim + c];
    g_mean[c] = s * (1.0f / (float)MTOT);
}

// ---------------- 2) Gram via mma.sync: 3 tiles x 64 K-splits ----------------
#define GP 144  // gram smem row pitch (64 bf16 = 128B + 16B pad)
__device__ __forceinline__ void gram_prefetch(uint32_t offA, uint32_t offB,
                                              const char* Ag, const char* Bg,
                                              int t, int kb, bool diag) {
#pragma unroll
    for (int i = 0; i < 4; ++i) {
        int slot = t + 256 * i;
        int row = slot >> 3, c16 = (slot & 7) * 16;
        cpasync16(offA + row * GP + c16, Ag + (size_t)row * 8192 + kb + c16);
        if (!diag)
            cpasync16(offB + row * GP + c16, Bg + (size_t)row * 8192 + kb + c16);
    }
}

__global__ __launch_bounds__(256) void gram_kernel() {
    extern __shared__ __align__(128) char sm[];
    const uint32_t sb = smem_u32(sm);
    const int t = threadIdx.x;
    const int warp = t >> 5, lane = t & 31;
    const int wm = warp >> 2, wn = warp & 3;  // 2 x 4 warp grid, warp tile 64x32
    const int tile = blockIdx.x, n = blockIdx.y;
    const int ti = (tile == 0) ? 0 : 1;
    const int tj = (tile == 2) ? 1 : 0;
    const bool diag = (tile != 1);
    const uint32_t offA[2] = {sb, sb + 36864};
    const uint32_t offB[2] = {sb + 18432, sb + 55296};

    const char* Ag = (const char*)(g_Xh + ((size_t)n * Cdim + ti * 128) * Ldim);
    const char* Bg = (const char*)(g_Xh + ((size_t)n * Cdim + tj * 128) * Ldim);

    float acc[4][4][4];
#pragma unroll
    for (int i = 0; i < 4; ++i)
#pragma unroll
        for (int j = 0; j < 4; ++j)
#pragma unroll
            for (int r = 0; r < 4; ++r) acc[i][j][r] = 0.0f;

    gram_prefetch(offA[0], offB[0], Ag, Bg, t, 0, diag);
    cpcommit();
    gram_prefetch(offA[1], offB[1], Ag, Bg, t, 128, diag);
    cpcommit();

    for (int s = 0; s < 64; ++s) {
        if (s == 63) cpwait<0>(); else cpwait<1>();
        __syncthreads();
        const uint32_t sa = offA[s & 1];
        const uint32_t sbuf = diag ? sa : offB[s & 1];
#pragma unroll
        for (int ks = 0; ks < 4; ++ks) {
            uint32_t afrag[4][4], bfrag[4][2];
#pragma unroll
            for (int mi = 0; mi < 4; ++mi)
                ldsm4(afrag[mi], sa + (wm * 64 + mi * 16 + (lane & 15)) * GP +
                                     ks * 32 + ((lane >> 4) * 16));
#pragma unroll
            for (int ni = 0; ni < 4; ++ni)
                ldsm2(bfrag[ni], sbuf + (wn * 32 + ni * 8 + (lane & 7)) * GP +
                                     ks * 32 + (((lane >> 3) & 1) * 16));
#pragma unroll
            for (int mi = 0; mi < 4; ++mi)
#pragma unroll
                for (int ni = 0; ni < 4; ++ni)
                    mma16816(acc[mi][ni], afrag[mi], bfrag[ni]);
        }
        __syncthreads();
        if (s + 2 < 64) {
            gram_prefetch(offA[s & 1], offB[s & 1], Ag, Bg, t, (s + 2) * 128, diag);
            cpcommit();
        }
    }

    float* outp = g_part[tile][n];
#pragma unroll
    for (int mi = 0; mi < 4; ++mi)
#pragma unroll
        for (int ni = 0; ni < 4; ++ni) {
            int r0 = wm * 64 + mi * 16 + (lane >> 2);
            int c0 = wn * 32 + ni * 8 + (lane & 3) * 2;
            *(float2*)(outp + r0 * 128 + c0)       = make_float2(acc[mi][ni][0], acc[mi][ni][1]);
            *(float2*)(outp + (r0 + 8) * 128 + c0) = make_float2(acc[mi][ni][2], acc[mi][ni][3]);
        }
}

// ---------------- 3) sigma assembly ----------------
__global__ void sigma_kernel() {
    const int idx = blockIdx.x * 256 + threadIdx.x;
    const int i = idx >> 8, j = idx & 255;
    int tile, ii, jj;
    if (i < 128 && j < 128)        { tile = 0; ii = i;       jj = j; }
    else if (i >= 128 && j < 128)  { tile = 1; ii = i - 128; jj = j; }
    else if (i >= 128 && j >= 128) { tile = 2; ii = i - 128; jj = j - 128; }
    else                           { tile = 1; ii = j - 128; jj = i; }  // symmetry
    float s = 0.0f;
#pragma unroll 16
    for (int n = 0; n < Nb; ++n) s += g_part[tile][n][ii * 128 + jj];
    float v = s * (1.0f / (float)MTOT) - g_mean[i] * g_mean[j];
    if (i == j) v += 1e-3f;
    g_sigma[idx] = v;
}

__global__ void trace_kernel() {
    __shared__ float red[256];
    const int t = threadIdx.x;
    red[t] = g_sigma[t * 257];
    __syncthreads();
    for (int o = 128; o > 0; o >>= 1) {
        if (t < o) red[t] += red[t + o];
        __syncthreads();
    }
    if (t == 0) {
        float s = red[0] * (1.0f / 256.0f);
        g_scal[0] = 1.0f / s;
        g_scal[1] = rsqrtf(s);
    }
}

__global__ void init_kernel() {
    const int idx = blockIdx.x * 256 + threadIdx.x;
    g_NS[0][idx] = g_sigma[idx] * g_scal[0];
    g_NS[2][idx] = ((idx >> 8) == (idx & 255)) ? 1.0f : 0.0f;
}

// ---------------- 4) fp32 256^3 GEMM body for Newton-Schulz ----------------
__device__ __forceinline__ void ns_body(int tileIdx, const float* A, const float* B,
                                        float* Cm, float alpha, float beta) {
    const int ti = tileIdx >> 2, tj = tileIdx & 3;
    __shared__ float As[64][17];
    __shared__ float Bs[16][68];
    const int t = threadIdx.x;
    const int tx = t & 15, ty = t >> 4;
    float acc[4][4] = {};
    for (int k0 = 0; k0 < 256; k0 += 16) {
        float4 av = *(const float4*)(A + (size_t)(ti * 64 + (t >> 2)) * 256 + k0 + ((t & 3) << 2));
        float4 bv = *(const float4*)(B + (size_t)(k0 + (t >> 4)) * 256 + tj * 64 + ((t & 15) << 2));
        __syncthreads();
        {
            const int ar = t >> 2, ak = (t & 3) << 2;
            As[ar][ak + 0] = av.x; As[ar][ak + 1] = av.y; As[ar][ak + 2] = av.z; As[ar][ak + 3] = av.w;
            *(float4*)&Bs[t >> 4][(t & 15) << 2] = bv;
        }
        __syncthreads();
#pragma unroll
        for (int k = 0; k < 16; ++k) {
            float4 b = *(const float4*)&Bs[k][tx << 2];
            float a0 = As[ty * 4 + 0][k], a1 = As[ty * 4 + 1][k];
            float a2 = As[ty * 4 + 2][k], a3 = As[ty * 4 + 3][k];
            acc[0][0] += a0 * b.x; acc[0][1] += a0 * b.y; acc[0][2] += a0 * b.z; acc[0][3] += a0 * b.w;
            acc[1][0] += a1 * b.x; acc[1][1] += a1 * b.y; acc[1][2] += a1 * b.z; acc[1][3] += a1 * b.w;
            acc[2][0] += a2 * b.x; acc[2][1] += a2 * b.y; acc[2][2] += a2 * b.z; acc[2][3] += a2 * b.w;
            acc[3][0] += a3 * b.x; acc[3][1] += a3 * b.y; acc[3][2] += a3 * b.z; acc[3][3] += a3 * b.w;
        }
    }
#pragma unroll
    for (int i = 0; i < 4; ++i)
#pragma unroll
        for (int j = 0; j < 4; ++j) {
            const int gi = ti * 64 + ty * 4 + i;
            const int gj = tj * 64 + tx * 4 + j;
            Cm[(size_t)gi * 256 + gj] = alpha * acc[i][j] + ((gi == gj) ? beta : 0.0f);
        }
}

__global__ void ns_T(int iz, int iy) {  // T = 3I - Z@Y
    ns_body(blockIdx.x, g_NS[iz], g_NS[iy], g_NS[4], -1.0f, 3.0f);
}
__global__ void ns_YZ(int iy, int iz) {  // Y' = 0.5 Y@T ; Z' = 0.5 T@Z
    if (blockIdx.x < 16)
        ns_body(blockIdx.x, g_NS[iy], g_NS[4], g_NS[iy ^ 1], 0.5f, 0.0f);
    else
        ns_body(blockIdx.x - 16, g_NS[4], g_NS[iz], g_NS[iz ^ 1], 0.5f, 0.0f);
}

// ---------------- 5) E = sc*Z - I (bf16) and b = mu + E mu ----------------
__global__ void bE_kernel(int iz) {
    const int c = blockIdx.x, t = threadIdx.x;
    const float sc = g_scal[1];
    float e = sc * g_NS[iz][c * 256 + t] - ((c == t) ? 1.0f : 0.0f);
    g_Ebf[c * 256 + t] = __float2bfloat16(e);
    __shared__ float red[256];
    red[t] = e * g_mean[t];
    __syncthreads();
    for (int o = 128; o > 0; o >>= 1) {
        if (t < o) red[t] += red[t + o];
        __syncthreads();
    }
    if (t == 0) g_b[c] = g_mean[c] + red[0];
}

// ---------------- 6) whiten: out = x - b + E @ x_bf16 (K-pipelined mma.sync) ----------------
#define WPA 144  // E chunk pitch: 64 bf16 = 128B + 16
#define WPB 272  // x chunk pitch: 128 bf16 = 256B + 16
#define WSA (256 * WPA)          // 36864
#define WSB (64 * WPB)           // 17408
#define WSTAGE (WSA + WSB)       // 54272

__device__ __forceinline__ void whiten_prefetch(uint32_t offA, uint32_t offB,
                                                const char* Eg, const char* Bg,
                                                int t, int kc) {
    // A: E[0:256, kc*64:(kc+1)*64] -> 256 rows x 128B
#pragma unroll
    for (int i = 0; i < 4; ++i) {
        int slot = t + 512 * i;
        int row = slot >> 3, c16 = (slot & 7) * 16;
        cpasync16(offA + row * WPA + c16, Eg + (size_t)row * 512 + kc * 128 + c16);
    }
    // B: x_bf16[kc*64:(kc+1)*64, l0:l0+128] -> 64 rows x 256B
#pragma unroll
    for (int i = 0; i < 2; ++i) {
        int slot = t + 512 * i;
        int row = slot >> 4, c16 = (slot & 15) * 16;
        cpasync16(offB + row * WPB + c16, Bg + (size_t)(kc * 64 + row) * 8192 + c16);
    }
}

__global__ __launch_bounds__(512) void whiten_kernel(const float* __restrict__ X,
                                                     float* __restrict__ out) {
    extern __shared__ __align__(128) char sm[];
    const uint32_t sb = smem_u32(sm);
    const int t = threadIdx.x;
    const int warp = t >> 5, lane = t & 31;
    const int wm = warp >> 2, wn = warp & 3;  // 4 x 4 warp grid, warp tile 64x32
    const int n = blockIdx.x >> 5, l0 = (blockIdx.x & 31) * 128;
    const uint32_t offA[2] = {sb, sb + WSTAGE};
    const uint32_t offB[2] = {sb + WSA, sb + WSTAGE + WSA};

    const char* Eg = (const char*)g_Ebf;
    const char* Bg = (const char*)(g_Xh + (size_t)n * Cdim * Ldim + l0);

    float acc[4][4][4];
#pragma unroll
    for (int i = 0; i < 4; ++i)
#pragma unroll
        for (int j = 0; j < 4; ++j)
#pragma unroll
            for (int r = 0; r < 4; ++r) acc[i][j][r] = 0.0f;

    whiten_prefetch(offA[0], offB[0], Eg, Bg, t, 0);
    cpcommit();
    whiten_prefetch(offA[1], offB[1], Eg, Bg, t, 1);
    cpcommit();

    for (int kc = 0; kc < 4; ++kc) {
        if (kc == 3) cpwait<0>(); else cpwait<1>();
        __syncthreads();
        const uint32_t sA = offA[kc & 1], sB = offB[kc & 1];
#pragma unroll
        for (int ks = 0; ks < 4; ++ks) {
            uint32_t afrag[4][4], bfrag[4][2];
#pragma unroll
            for (int mi = 0; mi < 4; ++mi)
                ldsm4(afrag[mi], sA + (wm * 64 + mi * 16 + (lane & 15)) * WPA +
                                     ks * 32 + ((lane >> 4) * 16));
#pragma unroll
            for (int ni = 0; ni < 4; ++ni)
                ldsm2t(bfrag[ni], sB + (ks * 16 + (lane & 15)) * WPB +
                                      (wn * 32 + ni * 8) * 2);
#pragma unroll
            for (int mi = 0; mi < 4; ++mi)
#pragma unroll
                for (int ni = 0; ni < 4; ++ni)
                    mma16816(acc[mi][ni], afrag[mi], bfrag[ni]);
        }
        __syncthreads();
        if (kc + 2 < 4) {
            whiten_prefetch(offA[kc & 1], offB[kc & 1], Eg, Bg, t, kc + 2);
            cpcommit();
        }
    }

    // epilogue: out[c][l] = acc + x - b
#pragma unroll
    for (int mi = 0; mi < 4; ++mi) {
        const int r0 = wm * 64 + mi * 16 + (lane >> 2);
        const float b0 = g_b[r0], b1 = g_b[r0 + 8];
        const float* x0 = X + ((size_t)n * Cdim + r0) * Ldim + l0;
        float* o0 = out + ((size_t)n * Cdim + r0) * Ldim + l0;
#pragma unroll
        for (int ni = 0; ni < 4; ++ni) {
            const int c = wn * 32 + ni * 8 + (lane & 3) * 2;
            float2 xv0 = *(const float2*)(x0 + c);
            float2 xv1 = *(const float2*)(x0 + 8 * Ldim + c);
            float2 ov0, ov1;
            ov0.x = acc[mi][ni][0] + xv0.x - b0;
            ov0.y = acc[mi][ni][1] + xv0.y - b0;
            ov1.x = acc[mi][ni][2] + xv1.x - b1;
            ov1.y = acc[mi][ni][3] + xv1.y - b1;
            *(float2*)(o0 + c) = ov0;
            *(float2*)(o0 + 8 * Ldim + c) = ov1;
        }
    }
}

// ---------------- launch ----------------
extern "C" void kernel_launch(void* const* d_in, const int* in_sizes, int n_in,
                              void* d_out, int out_size) {
    const float* X = (const float*)d_in[0];
    float* out = (float*)d_out;

    cudaFuncSetAttribute(gram_kernel, cudaFuncAttributeMaxDynamicSharedMemorySize, 73728);
    cudaFuncSetAttribute(whiten_kernel, cudaFuncAttributeMaxDynamicSharedMemorySize, 2 * WSTAGE);

    conv_kernel<<<Nb * Cdim, 256>>>(X);
    mean_reduce<<<1, 256>>>();
    gram_kernel<<<dim3(3, Nb), 256, 73728>>>();
    sigma_kernel<<<256, 256>>>();
    trace_kernel<<<1, 256>>>();
    init_kernel<<<256, 256>>>();

    int y = 0, z = 2;
    for (int it = 0; it < 3; ++it) {
        ns_T<<<16, 256>>>(z, y);
        ns_YZ<<<32, 256>>>(y, z);
        y ^= 1;
        z ^= 1;
    }

    bE_kernel<<<256, 256>>>(z);
    whiten_kernel<<<2048, 512, 2 * WSTAGE>>>(X, out);
}